// round 1
// baseline (speedup 1.0000x reference)
#include <cuda_runtime.h>
#include <math.h>

// Problem shape constants
#define BATCH 8
#define NX    2048
#define MMEM  256
#define TT    2304          // NX + MMEM
#define DD    512
#define D3    1536          // 3*DD

// Scratch (allocation-free: __device__ globals)
__device__ float g_XM [(size_t)BATCH * TT * DD];   //  37.7 MB
__device__ float g_QKV[(size_t)BATCH * TT * D3];   // 113.2 MB
__device__ float g_S  [(size_t)BATCH * TT * TT];   // 169.9 MB

// ---------------------------------------------------------------------------
// Build concatenated input XM[b,t,d]: x rows then transposed memory tokens
// ---------------------------------------------------------------------------
__global__ void build_xm_kernel(const float* __restrict__ x,
                                const float* __restrict__ mem) {
    size_t idx = (size_t)blockIdx.x * blockDim.x + threadIdx.x;
    const size_t total = (size_t)BATCH * TT * DD;
    if (idx >= total) return;
    int d = (int)(idx % DD);
    size_t bt = idx / DD;
    int t = (int)(bt % TT);
    int b = (int)(bt / TT);
    float v;
    if (t < NX) v = x[((size_t)b * NX + t) * DD + d];
    else        v = mem[(size_t)d * MMEM + (t - NX)];   // mem[0, d, t-NX]
    g_XM[idx] = v;
}

// ---------------------------------------------------------------------------
// NT GEMM: C[m,n] = alpha * sum_k A[m*lda+k] * B[n*ldb+k]
// 128x128 tile, BK=16, 256 threads, 8x8 per thread. All dims divide evenly.
// ---------------------------------------------------------------------------
__global__ __launch_bounds__(256)
void gemm_nt_kernel(const float* __restrict__ A, const float* __restrict__ B,
                    float* __restrict__ C, int Kdim,
                    int lda, int ldb, int ldc, float alpha,
                    size_t strideA, size_t strideB, size_t strideC) {
    A += (size_t)blockIdx.z * strideA;
    B += (size_t)blockIdx.z * strideB;
    C += (size_t)blockIdx.z * strideC;
    const int m0 = blockIdx.y * 128;
    const int n0 = blockIdx.x * 128;
    const int tid = threadIdx.x;
    const int tx = tid & 15;     // n sub-tile
    const int ty = tid >> 4;     // m sub-tile

    __shared__ float As[16 * 132];   // [k][m], padded stride 132
    __shared__ float Bs[16 * 132];   // [k][n]

    float acc[8][8];
#pragma unroll
    for (int i = 0; i < 8; i++)
#pragma unroll
        for (int j = 0; j < 8; j++) acc[i][j] = 0.f;

    for (int k0 = 0; k0 < Kdim; k0 += 16) {
#pragma unroll
        for (int it = 0; it < 2; it++) {
            int idx  = tid + it * 256;      // 0..511
            int row  = idx >> 2;            // 0..127
            int c    = (idx & 3) << 2;      // 0,4,8,12
            float4 va = *reinterpret_cast<const float4*>(
                A + (size_t)(m0 + row) * lda + k0 + c);
            As[(c + 0) * 132 + row] = va.x;
            As[(c + 1) * 132 + row] = va.y;
            As[(c + 2) * 132 + row] = va.z;
            As[(c + 3) * 132 + row] = va.w;
            float4 vb = *reinterpret_cast<const float4*>(
                B + (size_t)(n0 + row) * ldb + k0 + c);
            Bs[(c + 0) * 132 + row] = vb.x;
            Bs[(c + 1) * 132 + row] = vb.y;
            Bs[(c + 2) * 132 + row] = vb.z;
            Bs[(c + 3) * 132 + row] = vb.w;
        }
        __syncthreads();
#pragma unroll
        for (int kk = 0; kk < 16; kk++) {
            float a[8], b[8];
#pragma unroll
            for (int i = 0; i < 8; i++) a[i] = As[kk * 132 + ty * 8 + i];
#pragma unroll
            for (int j = 0; j < 8; j++) b[j] = Bs[kk * 132 + tx * 8 + j];
#pragma unroll
            for (int i = 0; i < 8; i++)
#pragma unroll
                for (int j = 0; j < 8; j++)
                    acc[i][j] = fmaf(a[i], b[j], acc[i][j]);
        }
        __syncthreads();
    }
#pragma unroll
    for (int i = 0; i < 8; i++) {
#pragma unroll
        for (int j = 0; j < 8; j += 4) {
            float4 v = make_float4(alpha * acc[i][j],     alpha * acc[i][j + 1],
                                   alpha * acc[i][j + 2], alpha * acc[i][j + 3]);
            *reinterpret_cast<float4*>(
                C + (size_t)(m0 + ty * 8 + i) * ldc + n0 + tx * 8 + j) = v;
        }
    }
}

// ---------------------------------------------------------------------------
// TN GEMM: C[m,n] = alpha * sum_k A[k*lda+m] * B[k*ldb+n]
// ---------------------------------------------------------------------------
__global__ __launch_bounds__(256)
void gemm_tn_kernel(const float* __restrict__ A, const float* __restrict__ B,
                    float* __restrict__ C, int Kdim,
                    int lda, int ldb, int ldc, float alpha,
                    size_t strideA, size_t strideB, size_t strideC) {
    A += (size_t)blockIdx.z * strideA;
    B += (size_t)blockIdx.z * strideB;
    C += (size_t)blockIdx.z * strideC;
    const int m0 = blockIdx.y * 128;
    const int n0 = blockIdx.x * 128;
    const int tid = threadIdx.x;
    const int tx = tid & 15;
    const int ty = tid >> 4;

    __shared__ float As[16 * 132];
    __shared__ float Bs[16 * 132];

    float acc[8][8];
#pragma unroll
    for (int i = 0; i < 8; i++)
#pragma unroll
        for (int j = 0; j < 8; j++) acc[i][j] = 0.f;

    for (int k0 = 0; k0 < Kdim; k0 += 16) {
#pragma unroll
        for (int it = 0; it < 2; it++) {
            int idx = tid + it * 256;       // 0..511
            int r   = idx >> 5;             // 0..15 (k within tile)
            int c   = (idx & 31) << 2;      // 0..124
            float4 va = *reinterpret_cast<const float4*>(
                A + (size_t)(k0 + r) * lda + m0 + c);
            *reinterpret_cast<float4*>(&As[r * 132 + c]) = va;
            float4 vb = *reinterpret_cast<const float4*>(
                B + (size_t)(k0 + r) * ldb + n0 + c);
            *reinterpret_cast<float4*>(&Bs[r * 132 + c]) = vb;
        }
        __syncthreads();
#pragma unroll
        for (int kk = 0; kk < 16; kk++) {
            float a[8], b[8];
#pragma unroll
            for (int i = 0; i < 8; i++) a[i] = As[kk * 132 + ty * 8 + i];
#pragma unroll
            for (int j = 0; j < 8; j++) b[j] = Bs[kk * 132 + tx * 8 + j];
#pragma unroll
            for (int i = 0; i < 8; i++)
#pragma unroll
                for (int j = 0; j < 8; j++)
                    acc[i][j] = fmaf(a[i], b[j], acc[i][j]);
        }
        __syncthreads();
    }
#pragma unroll
    for (int i = 0; i < 8; i++) {
#pragma unroll
        for (int j = 0; j < 8; j += 4) {
            float4 v = make_float4(alpha * acc[i][j],     alpha * acc[i][j + 1],
                                   alpha * acc[i][j + 2], alpha * acc[i][j + 3]);
            *reinterpret_cast<float4*>(
                C + (size_t)(m0 + ty * 8 + i) * ldc + n0 + tx * 8 + j) = v;
        }
    }
}

// ---------------------------------------------------------------------------
// Row softmax over T=2304 columns (9 per thread at 256 threads), in place.
// ---------------------------------------------------------------------------
__global__ __launch_bounds__(256)
void softmax_rows_kernel(float* __restrict__ S) {
    float* row = S + (size_t)blockIdx.x * TT;
    const int tid = threadIdx.x;
    __shared__ float red[8];

    float v[9];
    float lmax = -1e30f;
#pragma unroll
    for (int it = 0; it < 9; it++) {
        v[it] = row[tid + it * 256];
        lmax = fmaxf(lmax, v[it]);
    }
#pragma unroll
    for (int o = 16; o; o >>= 1)
        lmax = fmaxf(lmax, __shfl_xor_sync(0xffffffffu, lmax, o));
    if ((tid & 31) == 0) red[tid >> 5] = lmax;
    __syncthreads();
    float m = red[0];
#pragma unroll
    for (int w = 1; w < 8; w++) m = fmaxf(m, red[w]);

    float e[9];
    float lsum = 0.f;
#pragma unroll
    for (int it = 0; it < 9; it++) {
        e[it] = __expf(v[it] - m);
        lsum += e[it];
    }
#pragma unroll
    for (int o = 16; o; o >>= 1)
        lsum += __shfl_xor_sync(0xffffffffu, lsum, o);
    __syncthreads();                   // done reading red (max) everywhere
    if ((tid & 31) == 0) red[tid >> 5] = lsum;
    __syncthreads();
    float Z = 0.f;
#pragma unroll
    for (int w = 0; w < 8; w++) Z += red[w];
    float inv = 1.0f / Z;
#pragma unroll
    for (int it = 0; it < 9; it++) row[tid + it * 256] = e[it] * inv;
}

// ---------------------------------------------------------------------------
// Launch: XM -> QKV -> S = Q K^T/sqrt(D) -> row softmax -> out = A^T V
// ---------------------------------------------------------------------------
extern "C" void kernel_launch(void* const* d_in, const int* in_sizes, int n_in,
                              void* d_out, int out_size) {
    (void)in_sizes; (void)n_in; (void)out_size;
    const float* x   = (const float*)d_in[0];
    const float* mem = (const float*)d_in[1];
    const float* w   = (const float*)d_in[2];
    float* out = (float*)d_out;

    float *XM = nullptr, *QKV = nullptr, *S = nullptr;
    cudaGetSymbolAddress((void**)&XM,  g_XM);
    cudaGetSymbolAddress((void**)&QKV, g_QKV);
    cudaGetSymbolAddress((void**)&S,   g_S);

    // 1) XM = concat(x, mem^T)
    {
        size_t total = (size_t)BATCH * TT * DD;
        build_xm_kernel<<<(unsigned)((total + 255) / 256), 256>>>(x, mem);
    }
    // 2) QKV = XM @ W^T   (M = B*T = 18432, N = 1536, K = 512)
    {
        dim3 grid(D3 / 128, (BATCH * TT) / 128, 1);
        gemm_nt_kernel<<<grid, 256>>>(XM, w, QKV, DD,
                                      DD, DD, D3, 1.0f, 0, 0, 0);
    }
    // 3) S[b,j,i] = Q[b,j,:] . K[b,i,:] / sqrt(D)   per batch (2304 x 2304)
    {
        dim3 grid(TT / 128, TT / 128, BATCH);
        const float scale = 0.044194173824159216f;  // 1/sqrt(512)
        gemm_nt_kernel<<<grid, 256>>>(QKV, QKV + DD, S, DD,
                                      D3, D3, TT, scale,
                                      (size_t)TT * D3, (size_t)TT * D3,
                                      (size_t)TT * TT);
    }
    // 4) row softmax of S (softmax over k-index i for each fixed q-index j)
    softmax_rows_kernel<<<BATCH * TT, 256>>>(S);
    // 5) out[b,i,d] = sum_j S[b,j,i] * V[b,j,d]   (A^T @ V, TN layout)
    {
        dim3 grid(DD / 128, TT / 128, BATCH);
        gemm_tn_kernel<<<grid, 256>>>(S, QKV + 2 * DD, out, TT,
                                      TT, D3, DD, 1.0f,
                                      (size_t)TT * TT, (size_t)TT * D3,
                                      (size_t)TT * DD);
    }
}

// round 2
// speedup vs baseline: 2.2037x; 2.2037x over previous
#include <cuda_runtime.h>
#include <math.h>
#include <stdint.h>

// Problem shape constants
#define BATCH 8
#define NX    2048
#define MMEM  256
#define TT    2304          // NX + MMEM
#define DD    512
#define D3    1536          // 3*DD

// Scratch (allocation-free: __device__ globals)
__device__ float g_XM [(size_t)BATCH * TT * DD];   //  37.7 MB
__device__ float g_QKV[(size_t)BATCH * TT * D3];   // 113.2 MB
__device__ float g_S  [(size_t)BATCH * TT * TT];   // 169.9 MB

// ---------------------------------------------------------------------------
// helpers
// ---------------------------------------------------------------------------
__device__ __forceinline__ uint32_t f2tf32(float f) {
    uint32_t r;
    asm("cvt.rna.tf32.f32 %0, %1;" : "=r"(r) : "f"(f));
    return r;
}

__device__ __forceinline__ void mma_tf32(float* c, const uint32_t* a, const uint32_t* b) {
    asm volatile(
        "mma.sync.aligned.m16n8k8.row.col.f32.tf32.tf32.f32 "
        "{%0,%1,%2,%3}, {%4,%5,%6,%7}, {%8,%9}, {%0,%1,%2,%3};\n"
        : "+f"(c[0]), "+f"(c[1]), "+f"(c[2]), "+f"(c[3])
        : "r"(a[0]), "r"(a[1]), "r"(a[2]), "r"(a[3]), "r"(b[0]), "r"(b[1]));
}

// ---------------------------------------------------------------------------
// Build concatenated input XM[b,t,d]: x rows then transposed memory tokens
// ---------------------------------------------------------------------------
__global__ void build_xm_kernel(const float* __restrict__ x,
                                const float* __restrict__ mem) {
    size_t idx = (size_t)blockIdx.x * blockDim.x + threadIdx.x;
    const size_t total = (size_t)BATCH * TT * DD;
    if (idx >= total) return;
    int d = (int)(idx % DD);
    size_t bt = idx / DD;
    int t = (int)(bt % TT);
    int b = (int)(bt / TT);
    float v;
    if (t < NX) v = x[((size_t)b * NX + t) * DD + d];
    else        v = mem[(size_t)d * MMEM + (t - NX)];   // mem[0, d, t-NX]
    g_XM[idx] = v;
}

// ---------------------------------------------------------------------------
// Shared MMA tile compute: smem As[k][m] / Bs[k][n], stride 132 (uint32 tf32).
// Block 128x128, 8 warps in 2(m) x 4(n), warp tile 64x32, K-chunk 16.
// Fragment bank pattern 4*tg + g -> conflict-free with stride 132 (mod 32 = 4).
// ---------------------------------------------------------------------------
#define SMSTRIDE 132

__device__ __forceinline__ void mma_compute_chunk(
    const uint32_t* __restrict__ As, const uint32_t* __restrict__ Bs,
    int mBase, int nBase, int g, int tg, float acc[4][4][4]) {
#pragma unroll
    for (int s = 0; s < 2; s++) {           // two k8 steps per 16-chunk
        uint32_t a[4][4], b[4][2];
        const int kr0 = (s * 8 + tg) * SMSTRIDE;
        const int kr1 = (s * 8 + tg + 4) * SMSTRIDE;
#pragma unroll
        for (int mi = 0; mi < 4; mi++) {
            int m = mBase + mi * 16 + g;
            a[mi][0] = As[kr0 + m];
            a[mi][1] = As[kr0 + m + 8];
            a[mi][2] = As[kr1 + m];
            a[mi][3] = As[kr1 + m + 8];
        }
#pragma unroll
        for (int ni = 0; ni < 4; ni++) {
            int n = nBase + ni * 8 + g;
            b[ni][0] = Bs[kr0 + n];
            b[ni][1] = Bs[kr1 + n];
        }
#pragma unroll
        for (int mi = 0; mi < 4; mi++)
#pragma unroll
            for (int ni = 0; ni < 4; ni++)
                mma_tf32(acc[mi][ni], a[mi], b[ni]);
    }
}

__device__ __forceinline__ void mma_store_acc(
    float* __restrict__ C, int ldc, int m0, int n0,
    int mBase, int nBase, int g, int tg, float alpha, float acc[4][4][4]) {
#pragma unroll
    for (int mi = 0; mi < 4; mi++) {
        int r0 = m0 + mBase + mi * 16 + g;
#pragma unroll
        for (int ni = 0; ni < 4; ni++) {
            int cb = n0 + nBase + ni * 8 + 2 * tg;
            float2 v0 = make_float2(alpha * acc[mi][ni][0], alpha * acc[mi][ni][1]);
            float2 v1 = make_float2(alpha * acc[mi][ni][2], alpha * acc[mi][ni][3]);
            *reinterpret_cast<float2*>(C + (size_t)r0 * ldc + cb) = v0;
            *reinterpret_cast<float2*>(C + (size_t)(r0 + 8) * ldc + cb) = v1;
        }
    }
}

// ---------------------------------------------------------------------------
// NT GEMM (tf32 tensor cores): C[m,n] = alpha * sum_k A[m*lda+k] * B[n*ldb+k]
// ---------------------------------------------------------------------------
__global__ __launch_bounds__(256)
void gemm_nt_mma(const float* __restrict__ A, const float* __restrict__ B,
                 float* __restrict__ C, int Kdim,
                 int lda, int ldb, int ldc, float alpha,
                 size_t strideA, size_t strideB, size_t strideC) {
    A += (size_t)blockIdx.z * strideA;
    B += (size_t)blockIdx.z * strideB;
    C += (size_t)blockIdx.z * strideC;
    const int m0 = blockIdx.y * 128;
    const int n0 = blockIdx.x * 128;
    const int tid = threadIdx.x;
    const int lane = tid & 31;
    const int wid = tid >> 5;
    const int wm = wid & 1, wn = wid >> 1;     // 2 x 4 warp grid
    const int g = lane >> 2, tg = lane & 3;
    const int mBase = wm * 64, nBase = wn * 32;

    __shared__ uint32_t As[16 * SMSTRIDE];
    __shared__ uint32_t Bs[16 * SMSTRIDE];

    // global load indices: idx = tid + it*256; row 0..127; c4 in {0,4,8,12}
    const int row0 = tid >> 2;
    const int c4   = (tid & 3) << 2;

    float acc[4][4][4];
#pragma unroll
    for (int mi = 0; mi < 4; mi++)
#pragma unroll
        for (int ni = 0; ni < 4; ni++)
#pragma unroll
            for (int q = 0; q < 4; q++) acc[mi][ni][q] = 0.f;

    float4 pa[2], pb[2];
    // prologue: prefetch chunk 0
#pragma unroll
    for (int it = 0; it < 2; it++) {
        int row = row0 + it * 64;
        pa[it] = *reinterpret_cast<const float4*>(A + (size_t)(m0 + row) * lda + c4);
        pb[it] = *reinterpret_cast<const float4*>(B + (size_t)(n0 + row) * ldb + c4);
    }

    for (int k0 = 0; k0 < Kdim; k0 += 16) {
        // store prefetched chunk to smem (tf32-converted, transposed to [k][m])
#pragma unroll
        for (int it = 0; it < 2; it++) {
            int row = row0 + it * 64;
            As[(c4 + 0) * SMSTRIDE + row] = f2tf32(pa[it].x);
            As[(c4 + 1) * SMSTRIDE + row] = f2tf32(pa[it].y);
            As[(c4 + 2) * SMSTRIDE + row] = f2tf32(pa[it].z);
            As[(c4 + 3) * SMSTRIDE + row] = f2tf32(pa[it].w);
            Bs[(c4 + 0) * SMSTRIDE + row] = f2tf32(pb[it].x);
            Bs[(c4 + 1) * SMSTRIDE + row] = f2tf32(pb[it].y);
            Bs[(c4 + 2) * SMSTRIDE + row] = f2tf32(pb[it].z);
            Bs[(c4 + 3) * SMSTRIDE + row] = f2tf32(pb[it].w);
        }
        __syncthreads();
        // prefetch next chunk while computing this one
        if (k0 + 16 < Kdim) {
#pragma unroll
            for (int it = 0; it < 2; it++) {
                int row = row0 + it * 64;
                pa[it] = *reinterpret_cast<const float4*>(
                    A + (size_t)(m0 + row) * lda + k0 + 16 + c4);
                pb[it] = *reinterpret_cast<const float4*>(
                    B + (size_t)(n0 + row) * ldb + k0 + 16 + c4);
            }
        }
        mma_compute_chunk(As, Bs, mBase, nBase, g, tg, acc);
        __syncthreads();
    }
    mma_store_acc(C, ldc, m0, n0, mBase, nBase, g, tg, alpha, acc);
}

// ---------------------------------------------------------------------------
// TN GEMM (tf32 tensor cores): C[m,n] = alpha * sum_k A[k*lda+m] * B[k*ldb+n]
// ---------------------------------------------------------------------------
__global__ __launch_bounds__(256)
void gemm_tn_mma(const float* __restrict__ A, const float* __restrict__ B,
                 float* __restrict__ C, int Kdim,
                 int lda, int ldb, int ldc, float alpha,
                 size_t strideA, size_t strideB, size_t strideC) {
    A += (size_t)blockIdx.z * strideA;
    B += (size_t)blockIdx.z * strideB;
    C += (size_t)blockIdx.z * strideC;
    const int m0 = blockIdx.y * 128;
    const int n0 = blockIdx.x * 128;
    const int tid = threadIdx.x;
    const int lane = tid & 31;
    const int wid = tid >> 5;
    const int wm = wid & 1, wn = wid >> 1;
    const int g = lane >> 2, tg = lane & 3;
    const int mBase = wm * 64, nBase = wn * 32;

    __shared__ uint32_t As[16 * SMSTRIDE];
    __shared__ uint32_t Bs[16 * SMSTRIDE];

    // global load indices: idx = tid + it*256; r = k within tile, c = 4-col group
    const int r0 = tid >> 5;            // 0..7 (+8 for it=1)
    const int cc = (tid & 31) << 2;     // 0..124

    float acc[4][4][4];
#pragma unroll
    for (int mi = 0; mi < 4; mi++)
#pragma unroll
        for (int ni = 0; ni < 4; ni++)
#pragma unroll
            for (int q = 0; q < 4; q++) acc[mi][ni][q] = 0.f;

    float4 pa[2], pb[2];
#pragma unroll
    for (int it = 0; it < 2; it++) {
        int r = r0 + it * 8;
        pa[it] = *reinterpret_cast<const float4*>(A + (size_t)r * lda + m0 + cc);
        pb[it] = *reinterpret_cast<const float4*>(B + (size_t)r * ldb + n0 + cc);
    }

    for (int k0 = 0; k0 < Kdim; k0 += 16) {
#pragma unroll
        for (int it = 0; it < 2; it++) {
            int r = r0 + it * 8;
            uint4 ua = make_uint4(f2tf32(pa[it].x), f2tf32(pa[it].y),
                                  f2tf32(pa[it].z), f2tf32(pa[it].w));
            uint4 ub = make_uint4(f2tf32(pb[it].x), f2tf32(pb[it].y),
                                  f2tf32(pb[it].z), f2tf32(pb[it].w));
            *reinterpret_cast<uint4*>(&As[r * SMSTRIDE + cc]) = ua;
            *reinterpret_cast<uint4*>(&Bs[r * SMSTRIDE + cc]) = ub;
        }
        __syncthreads();
        if (k0 + 16 < Kdim) {
#pragma unroll
            for (int it = 0; it < 2; it++) {
                int r = k0 + 16 + r0 + it * 8;
                pa[it] = *reinterpret_cast<const float4*>(A + (size_t)r * lda + m0 + cc);
                pb[it] = *reinterpret_cast<const float4*>(B + (size_t)r * ldb + n0 + cc);
            }
        }
        mma_compute_chunk(As, Bs, mBase, nBase, g, tg, acc);
        __syncthreads();
    }
    mma_store_acc(C, ldc, m0, n0, mBase, nBase, g, tg, alpha, acc);
}

// ---------------------------------------------------------------------------
// Row softmax over T=2304 columns (9 per thread at 256 threads), in place.
// ---------------------------------------------------------------------------
__global__ __launch_bounds__(256)
void softmax_rows_kernel(float* __restrict__ S) {
    float* row = S + (size_t)blockIdx.x * TT;
    const int tid = threadIdx.x;
    __shared__ float red[8];

    float v[9];
    float lmax = -1e30f;
#pragma unroll
    for (int it = 0; it < 9; it++) {
        v[it] = row[tid + it * 256];
        lmax = fmaxf(lmax, v[it]);
    }
#pragma unroll
    for (int o = 16; o; o >>= 1)
        lmax = fmaxf(lmax, __shfl_xor_sync(0xffffffffu, lmax, o));
    if ((tid & 31) == 0) red[tid >> 5] = lmax;
    __syncthreads();
    float m = red[0];
#pragma unroll
    for (int w = 1; w < 8; w++) m = fmaxf(m, red[w]);

    float e[9];
    float lsum = 0.f;
#pragma unroll
    for (int it = 0; it < 9; it++) {
        e[it] = __expf(v[it] - m);
        lsum += e[it];
    }
#pragma unroll
    for (int o = 16; o; o >>= 1)
        lsum += __shfl_xor_sync(0xffffffffu, lsum, o);
    __syncthreads();                   // done reading red (max) everywhere
    if ((tid & 31) == 0) red[tid >> 5] = lsum;
    __syncthreads();
    float Z = 0.f;
#pragma unroll
    for (int w = 0; w < 8; w++) Z += red[w];
    float inv = 1.0f / Z;
#pragma unroll
    for (int it = 0; it < 9; it++) row[tid + it * 256] = e[it] * inv;
}

// ---------------------------------------------------------------------------
// Launch: XM -> QKV -> S = Q K^T/sqrt(D) -> row softmax -> out = A^T V
// ---------------------------------------------------------------------------
extern "C" void kernel_launch(void* const* d_in, const int* in_sizes, int n_in,
                              void* d_out, int out_size) {
    (void)in_sizes; (void)n_in; (void)out_size;
    const float* x   = (const float*)d_in[0];
    const float* mem = (const float*)d_in[1];
    const float* w   = (const float*)d_in[2];
    float* out = (float*)d_out;

    float *XM = nullptr, *QKV = nullptr, *S = nullptr;
    cudaGetSymbolAddress((void**)&XM,  g_XM);
    cudaGetSymbolAddress((void**)&QKV, g_QKV);
    cudaGetSymbolAddress((void**)&S,   g_S);

    // 1) XM = concat(x, mem^T)
    {
        size_t total = (size_t)BATCH * TT * DD;
        build_xm_kernel<<<(unsigned)((total + 255) / 256), 256>>>(x, mem);
    }
    // 2) QKV = XM @ W^T   (M = B*T = 18432, N = 1536, K = 512)
    {
        dim3 grid(D3 / 128, (BATCH * TT) / 128, 1);
        gemm_nt_mma<<<grid, 256>>>(XM, w, QKV, DD,
                                   DD, DD, D3, 1.0f, 0, 0, 0);
    }
    // 3) S[b,j,i] = Q[b,j,:] . K[b,i,:] / sqrt(D)   per batch (2304 x 2304)
    {
        dim3 grid(TT / 128, TT / 128, BATCH);
        const float scale = 0.044194173824159216f;  // 1/sqrt(512)
        gemm_nt_mma<<<grid, 256>>>(QKV, QKV + DD, S, DD,
                                   D3, D3, TT, scale,
                                   (size_t)TT * D3, (size_t)TT * D3,
                                   (size_t)TT * TT);
    }
    // 4) row softmax of S (softmax over k-index i for each fixed q-index j)
    softmax_rows_kernel<<<BATCH * TT, 256>>>(S);
    // 5) out[b,i,d] = sum_j S[b,j,i] * V[b,j,d]   (A^T @ V, TN layout)
    {
        dim3 grid(DD / 128, TT / 128, BATCH);
        gemm_tn_mma<<<grid, 256>>>(S, QKV + 2 * DD, out, TT,
                                   TT, D3, DD, 1.0f,
                                   (size_t)TT * TT, (size_t)TT * D3,
                                   (size_t)TT * DD);
    }
}

// round 3
// speedup vs baseline: 4.5860x; 2.0810x over previous
#include <cuda_runtime.h>
#include <cuda_fp16.h>
#include <math.h>
#include <stdint.h>

// Problem shape constants
#define BATCH 8
#define NX    2048
#define MMEM  256
#define TT    2304          // NX + MMEM
#define DD    512
#define D3    1536          // 3*DD

// Scratch (allocation-free: __device__ globals)
__device__ __half g_XM [(size_t)BATCH * TT * DD];   // 18.9 MB fp16
__device__ __half g_W  [(size_t)D3 * DD];           //  1.5 MB fp16
__device__ __half g_QKV[(size_t)BATCH * TT * D3];   // 56.6 MB fp16
__device__ float  g_S  [(size_t)BATCH * TT * TT];   // 169.9 MB fp32 logits
__device__ __half g_P  [(size_t)BATCH * TT * TT];   // 85.0 MB fp16 probs

// ---------------------------------------------------------------------------
// PTX helpers
// ---------------------------------------------------------------------------
__device__ __forceinline__ void mma_f16(float* c, const uint32_t* a, const uint32_t* b) {
    asm volatile(
        "mma.sync.aligned.m16n8k16.row.col.f32.f16.f16.f32 "
        "{%0,%1,%2,%3}, {%4,%5,%6,%7}, {%8,%9}, {%0,%1,%2,%3};\n"
        : "+f"(c[0]), "+f"(c[1]), "+f"(c[2]), "+f"(c[3])
        : "r"(a[0]), "r"(a[1]), "r"(a[2]), "r"(a[3]), "r"(b[0]), "r"(b[1]));
}

__device__ __forceinline__ void ldsm4(uint32_t* r, const __half* p) {
    uint32_t addr = (uint32_t)__cvta_generic_to_shared(p);
    asm volatile("ldmatrix.sync.aligned.m8n8.x4.shared.b16 {%0,%1,%2,%3}, [%4];"
                 : "=r"(r[0]), "=r"(r[1]), "=r"(r[2]), "=r"(r[3]) : "r"(addr));
}

__device__ __forceinline__ void ldsm4t(uint32_t* r, const __half* p) {
    uint32_t addr = (uint32_t)__cvta_generic_to_shared(p);
    asm volatile("ldmatrix.sync.aligned.m8n8.x4.trans.shared.b16 {%0,%1,%2,%3}, [%4];"
                 : "=r"(r[0]), "=r"(r[1]), "=r"(r[2]), "=r"(r[3]) : "r"(addr));
}

// ---------------------------------------------------------------------------
// Input prep: XM = concat(x, mem^T) in fp16;  W -> fp16
// ---------------------------------------------------------------------------
__global__ void build_xm_half(const float* __restrict__ x,
                              const float* __restrict__ mem) {
    size_t idx = (size_t)blockIdx.x * blockDim.x + threadIdx.x;
    const size_t total = (size_t)BATCH * TT * DD;
    if (idx >= total) return;
    int d = (int)(idx % DD);
    size_t bt = idx / DD;
    int t = (int)(bt % TT);
    int b = (int)(bt / TT);
    float v;
    if (t < NX) v = x[((size_t)b * NX + t) * DD + d];
    else        v = mem[(size_t)d * MMEM + (t - NX)];   // mem[0, d, t-NX]
    g_XM[idx] = __float2half(v);
}

__global__ void cvt_w_half(const float* __restrict__ w) {
    size_t idx = (size_t)blockIdx.x * blockDim.x + threadIdx.x;
    if (idx < (size_t)D3 * DD) g_W[idx] = __float2half(w[idx]);
}

// ---------------------------------------------------------------------------
// NT GEMM (fp16 mma, fp32 acc): C[m,n] = alpha * sum_k A[m*lda+k] * B[n*ldb+k]
// Block 128x128, BK=32, 8 warps (2m x 4n), warp tile 64x32.
// smem layout [m][k] / [n][k], padded row stride 40 halves (conflict-free).
// ---------------------------------------------------------------------------
#define NTS 40

template <typename CT>
__global__ __launch_bounds__(256)
void gemm_nt_f16(const __half* __restrict__ A, const __half* __restrict__ B,
                 CT* __restrict__ C, int Kdim,
                 int lda, int ldb, int ldc, float alpha,
                 size_t sA, size_t sB, size_t sC) {
    A += (size_t)blockIdx.z * sA;
    B += (size_t)blockIdx.z * sB;
    C += (size_t)blockIdx.z * sC;
    const int m0 = blockIdx.y * 128;
    const int n0 = blockIdx.x * 128;
    const int tid = threadIdx.x;
    const int lane = tid & 31;
    const int wid = tid >> 5;
    const int mBase = (wid & 1) * 64;
    const int nBase = (wid >> 1) * 32;

    __shared__ __half As[128 * NTS];
    __shared__ __half Bs[128 * NTS];

    // global loads: 2 threads per row, 16 halves each
    const int grow = tid >> 1;
    const int gk   = (tid & 1) * 16;
    const __half* Ag = A + (size_t)(m0 + grow) * lda + gk;
    const __half* Bg = B + (size_t)(n0 + grow) * ldb + gk;

    // ldmatrix lane bases (in half units): row = base+(lane&15), k-col = 8*(lane>>4)
    const int aBase = (mBase + (lane & 15)) * NTS + 8 * (lane >> 4);
    const int bBase = (nBase + (lane & 15)) * NTS + 8 * (lane >> 4);

    float acc[4][4][4];
#pragma unroll
    for (int mi = 0; mi < 4; mi++)
#pragma unroll
        for (int ni = 0; ni < 4; ni++)
#pragma unroll
            for (int q = 0; q < 4; q++) acc[mi][ni][q] = 0.f;

    uint4 pa0 = *(const uint4*)(Ag);
    uint4 pa1 = *(const uint4*)(Ag + 8);
    uint4 pb0 = *(const uint4*)(Bg);
    uint4 pb1 = *(const uint4*)(Bg + 8);

    for (int k0 = 0; k0 < Kdim; k0 += 32) {
        *(uint4*)&As[grow * NTS + gk]     = pa0;
        *(uint4*)&As[grow * NTS + gk + 8] = pa1;
        *(uint4*)&Bs[grow * NTS + gk]     = pb0;
        *(uint4*)&Bs[grow * NTS + gk + 8] = pb1;
        __syncthreads();
        if (k0 + 32 < Kdim) {
            pa0 = *(const uint4*)(Ag + k0 + 32);
            pa1 = *(const uint4*)(Ag + k0 + 40);
            pb0 = *(const uint4*)(Bg + k0 + 32);
            pb1 = *(const uint4*)(Bg + k0 + 40);
        }
#pragma unroll
        for (int s = 0; s < 2; s++) {
            uint32_t af[4][4], bf[2][4];
#pragma unroll
            for (int mi = 0; mi < 4; mi++)
                ldsm4(af[mi], &As[aBase + mi * 16 * NTS + s * 16]);
#pragma unroll
            for (int u = 0; u < 2; u++)
                ldsm4(bf[u], &Bs[bBase + u * 16 * NTS + s * 16]);
#pragma unroll
            for (int mi = 0; mi < 4; mi++)
#pragma unroll
                for (int ni = 0; ni < 4; ni++) {
                    // x4 regs: r0=(n+0,k0) r1=(n+8,k0) r2=(n+0,k8) r3=(n+8,k8)
                    uint32_t bb[2] = { bf[ni >> 1][ni & 1], bf[ni >> 1][(ni & 1) + 2] };
                    mma_f16(acc[mi][ni], af[mi], bb);
                }
        }
        __syncthreads();
    }

    const int g = lane >> 2, tg = lane & 3;
#pragma unroll
    for (int mi = 0; mi < 4; mi++) {
        int r0 = m0 + mBase + mi * 16 + g;
#pragma unroll
        for (int ni = 0; ni < 4; ni++) {
            int cb = n0 + nBase + ni * 8 + 2 * tg;
            if constexpr (sizeof(CT) == 2) {
                __half2 v0 = __floats2half2_rn(alpha * acc[mi][ni][0], alpha * acc[mi][ni][1]);
                __half2 v1 = __floats2half2_rn(alpha * acc[mi][ni][2], alpha * acc[mi][ni][3]);
                *reinterpret_cast<__half2*>((__half*)C + (size_t)r0 * ldc + cb) = v0;
                *reinterpret_cast<__half2*>((__half*)C + (size_t)(r0 + 8) * ldc + cb) = v1;
            } else {
                float2 v0 = make_float2(alpha * acc[mi][ni][0], alpha * acc[mi][ni][1]);
                float2 v1 = make_float2(alpha * acc[mi][ni][2], alpha * acc[mi][ni][3]);
                *reinterpret_cast<float2*>((float*)C + (size_t)r0 * ldc + cb) = v0;
                *reinterpret_cast<float2*>((float*)C + (size_t)(r0 + 8) * ldc + cb) = v1;
            }
        }
    }
}

// ---------------------------------------------------------------------------
// TN GEMM (fp16 mma): C[m,n] = alpha * sum_k A[k*lda+m] * B[k*ldb+n], C fp32.
// smem layout [k][m] / [k][n], padded row stride 136 halves; ldmatrix.trans.
// ---------------------------------------------------------------------------
#define TNS 136

__global__ __launch_bounds__(256)
void gemm_tn_f16(const __half* __restrict__ A, const __half* __restrict__ B,
                 float* __restrict__ C, int Kdim,
                 int lda, int ldb, int ldc, float alpha,
                 size_t sA, size_t sB, size_t sC) {
    A += (size_t)blockIdx.z * sA;
    B += (size_t)blockIdx.z * sB;
    C += (size_t)blockIdx.z * sC;
    const int m0 = blockIdx.y * 128;
    const int n0 = blockIdx.x * 128;
    const int tid = threadIdx.x;
    const int lane = tid & 31;
    const int wid = tid >> 5;
    const int mBase = (wid & 1) * 64;
    const int nBase = (wid >> 1) * 32;

    __shared__ __half As[32 * TNS];
    __shared__ __half Bs[32 * TNS];

    // global loads: 8 threads per k-row, 16 halves each
    const int grow = tid >> 3;          // 0..31 (k)
    const int gc   = (tid & 7) * 16;    // 0..112
    const __half* Ag = A + m0 + gc;
    const __half* Bg = B + n0 + gc;

    // trans-ldmatrix lane bases (half units)
    // A frags: matrices (k0,m0),(k0,m8),(k8,m0),(k8,m8)
    const int aBase = ((lane & 7) + 8 * (lane >> 4)) * TNS + mBase + 8 * ((lane >> 3) & 1);
    // B frags: matrices (k0,n0),(k8,n0),(k0,n8),(k8,n8)
    const int bBase = ((lane & 7) + 8 * ((lane >> 3) & 1)) * TNS + nBase + 8 * (lane >> 4);

    float acc[4][4][4];
#pragma unroll
    for (int mi = 0; mi < 4; mi++)
#pragma unroll
        for (int ni = 0; ni < 4; ni++)
#pragma unroll
            for (int q = 0; q < 4; q++) acc[mi][ni][q] = 0.f;

    uint4 pa0 = *(const uint4*)(Ag + (size_t)grow * lda);
    uint4 pa1 = *(const uint4*)(Ag + (size_t)grow * lda + 8);
    uint4 pb0 = *(const uint4*)(Bg + (size_t)grow * ldb);
    uint4 pb1 = *(const uint4*)(Bg + (size_t)grow * ldb + 8);

    for (int k0 = 0; k0 < Kdim; k0 += 32) {
        *(uint4*)&As[grow * TNS + gc]     = pa0;
        *(uint4*)&As[grow * TNS + gc + 8] = pa1;
        *(uint4*)&Bs[grow * TNS + gc]     = pb0;
        *(uint4*)&Bs[grow * TNS + gc + 8] = pb1;
        __syncthreads();
        if (k0 + 32 < Kdim) {
            size_t ra = (size_t)(k0 + 32 + grow) * lda;
            size_t rb = (size_t)(k0 + 32 + grow) * ldb;
            pa0 = *(const uint4*)(Ag + ra);
            pa1 = *(const uint4*)(Ag + ra + 8);
            pb0 = *(const uint4*)(Bg + rb);
            pb1 = *(const uint4*)(Bg + rb + 8);
        }
#pragma unroll
        for (int s = 0; s < 2; s++) {
            uint32_t af[4][4], bf[2][4];
#pragma unroll
            for (int mi = 0; mi < 4; mi++)
                ldsm4t(af[mi], &As[aBase + s * 16 * TNS + mi * 16]);
#pragma unroll
            for (int u = 0; u < 2; u++)
                ldsm4t(bf[u], &Bs[bBase + s * 16 * TNS + u * 16]);
#pragma unroll
            for (int mi = 0; mi < 4; mi++)
#pragma unroll
                for (int ni = 0; ni < 4; ni++) {
                    // x4 regs: r0=(k0,n+0) r1=(k8,n+0) r2=(k0,n+8) r3=(k8,n+8)
                    uint32_t bb[2] = { bf[ni >> 1][2 * (ni & 1)], bf[ni >> 1][2 * (ni & 1) + 1] };
                    mma_f16(acc[mi][ni], af[mi], bb);
                }
        }
        __syncthreads();
    }

    const int g = lane >> 2, tg = lane & 3;
#pragma unroll
    for (int mi = 0; mi < 4; mi++) {
        int r0 = m0 + mBase + mi * 16 + g;
#pragma unroll
        for (int ni = 0; ni < 4; ni++) {
            int cb = n0 + nBase + ni * 8 + 2 * tg;
            float2 v0 = make_float2(alpha * acc[mi][ni][0], alpha * acc[mi][ni][1]);
            float2 v1 = make_float2(alpha * acc[mi][ni][2], alpha * acc[mi][ni][3]);
            *reinterpret_cast<float2*>(C + (size_t)r0 * ldc + cb) = v0;
            *reinterpret_cast<float2*>(C + (size_t)(r0 + 8) * ldc + cb) = v1;
        }
    }
}

// ---------------------------------------------------------------------------
// Row softmax over T=2304 columns: read fp32 logits, write fp16 probs.
// ---------------------------------------------------------------------------
__global__ __launch_bounds__(256)
void softmax_rows_kernel(const float* __restrict__ S, __half* __restrict__ P) {
    const float* row = S + (size_t)blockIdx.x * TT;
    __half* prow = P + (size_t)blockIdx.x * TT;
    const int tid = threadIdx.x;
    __shared__ float red[8];

    float v[9];
    float lmax = -1e30f;
#pragma unroll
    for (int it = 0; it < 9; it++) {
        v[it] = row[tid + it * 256];
        lmax = fmaxf(lmax, v[it]);
    }
#pragma unroll
    for (int o = 16; o; o >>= 1)
        lmax = fmaxf(lmax, __shfl_xor_sync(0xffffffffu, lmax, o));
    if ((tid & 31) == 0) red[tid >> 5] = lmax;
    __syncthreads();
    float m = red[0];
#pragma unroll
    for (int w = 1; w < 8; w++) m = fmaxf(m, red[w]);

    float e[9];
    float lsum = 0.f;
#pragma unroll
    for (int it = 0; it < 9; it++) {
        e[it] = __expf(v[it] - m);
        lsum += e[it];
    }
#pragma unroll
    for (int o = 16; o; o >>= 1)
        lsum += __shfl_xor_sync(0xffffffffu, lsum, o);
    __syncthreads();
    if ((tid & 31) == 0) red[tid >> 5] = lsum;
    __syncthreads();
    float Z = 0.f;
#pragma unroll
    for (int w = 0; w < 8; w++) Z += red[w];
    float inv = 1.0f / Z;
#pragma unroll
    for (int it = 0; it < 9; it++)
        prow[tid + it * 256] = __float2half(e[it] * inv);
}

// ---------------------------------------------------------------------------
// Launch: XM/W fp16 -> QKV -> S = Q K^T/sqrt(D) -> softmax -> out = P^T V
// ---------------------------------------------------------------------------
extern "C" void kernel_launch(void* const* d_in, const int* in_sizes, int n_in,
                              void* d_out, int out_size) {
    (void)in_sizes; (void)n_in; (void)out_size;
    const float* x   = (const float*)d_in[0];
    const float* mem = (const float*)d_in[1];
    const float* w   = (const float*)d_in[2];
    float* out = (float*)d_out;

    __half *XM = nullptr, *W = nullptr, *QKV = nullptr, *P = nullptr;
    float *S = nullptr;
    cudaGetSymbolAddress((void**)&XM,  g_XM);
    cudaGetSymbolAddress((void**)&W,   g_W);
    cudaGetSymbolAddress((void**)&QKV, g_QKV);
    cudaGetSymbolAddress((void**)&S,   g_S);
    cudaGetSymbolAddress((void**)&P,   g_P);

    // 1) prep fp16 inputs
    {
        size_t total = (size_t)BATCH * TT * DD;
        build_xm_half<<<(unsigned)((total + 255) / 256), 256>>>(x, mem);
        size_t wtot = (size_t)D3 * DD;
        cvt_w_half<<<(unsigned)((wtot + 255) / 256), 256>>>(w);
    }
    // 2) QKV = XM @ W^T   (M = 18432, N = 1536, K = 512), fp16 out
    {
        dim3 grid(D3 / 128, (BATCH * TT) / 128, 1);
        gemm_nt_f16<__half><<<grid, 256>>>(XM, W, QKV, DD,
                                           DD, DD, D3, 1.0f, 0, 0, 0);
    }
    // 3) S[b,j,i] = Q[b,j,:] . K[b,i,:] / sqrt(D), fp32 out (2304 x 2304 x8)
    {
        dim3 grid(TT / 128, TT / 128, BATCH);
        const float scale = 0.044194173824159216f;  // 1/sqrt(512)
        gemm_nt_f16<float><<<grid, 256>>>(QKV, QKV + DD, S, DD,
                                          D3, D3, TT, scale,
                                          (size_t)TT * D3, (size_t)TT * D3,
                                          (size_t)TT * TT);
    }
    // 4) row softmax: fp32 S -> fp16 P
    softmax_rows_kernel<<<BATCH * TT, 256>>>(S, P);
    // 5) out[b,i,d] = sum_j P[b,j,i] * V[b,j,d]   (TN, fp32 out)
    {
        dim3 grid(DD / 128, TT / 128, BATCH);
        gemm_tn_f16<<<grid, 256>>>(P, QKV + 2 * DD, out, TT,
                                   TT, D3, DD, 1.0f,
                                   (size_t)TT * TT, (size_t)TT * D3,
                                   (size_t)TT * DD);
    }
}